// round 8
// baseline (speedup 1.0000x reference)
#include <cuda_runtime.h>
#include <stdint.h>

#define NT 256            // 8 warps; 32 batch rows per warp
#define BATCH_PER_CTA 256

// ---- smem layout (bytes) ----
// bfrag: [2 mats][24 nt][4 kt][32 lanes] x uint4 = 98304
// tab:   [2 mats][64 j][4] x float4 = 8192   ({bias4, wir, wiz, wn})
// lwt:   [64] float4 = 1024 ; lnb 16
#define OFF_BF   0
#define OFF_TAB  98304
#define OFF_LWT  106496
#define OFF_LNB  107520
#define SMEM_TOTAL 107536

// ---------------- helpers ----------------
__device__ __forceinline__ uint32_t f2bf(float f) {
    uint16_t u;
    asm("cvt.rn.bf16.f32 %0, %1;" : "=h"(u) : "f"(f));
    return (uint32_t)u;
}
__device__ __forceinline__ float bfval(uint32_t u16) {
    return __uint_as_float(u16 << 16);
}
__device__ __forceinline__ float bfhi(uint32_t u32) {
    return __uint_as_float(u32 & 0xffff0000u);
}
__device__ __forceinline__ float bflo(uint32_t u32) {
    return __uint_as_float(u32 << 16);
}
__device__ __forceinline__ void split2(float va, float vb, uint32_t& hi, uint32_t& lo) {
    uint32_t ha = f2bf(va), hb = f2bf(vb);
    uint32_t la = f2bf(va - bfval(ha)), lb = f2bf(vb - bfval(hb));
    hi = ha | (hb << 16);
    lo = la | (lb << 16);
}
__device__ __forceinline__ float fex2(float x) {
    float r; asm("ex2.approx.f32 %0, %1;" : "=f"(r) : "f"(x)); return r;
}
__device__ __forceinline__ float frcp(float x) {
    float r; asm("rcp.approx.f32 %0, %1;" : "=f"(r) : "f"(x)); return r;
}
__device__ __forceinline__ float fsigmoid(float x) {
    return frcp(1.0f + fex2(-1.4426950408889634f * x));
}
__device__ __forceinline__ float ftanh(float x) {
    float a = fabsf(x);
    float t = 1.0f - 2.0f * frcp(fex2(2.8853900817779268f * a) + 1.0f);
    return copysignf(t, x);
}
__device__ __forceinline__ void mma16816(float* d, const uint32_t* a,
                                         uint32_t b0, uint32_t b1) {
    asm volatile(
        "mma.sync.aligned.m16n8k16.row.col.f32.bf16.bf16.f32 "
        "{%0,%1,%2,%3}, {%4,%5,%6,%7}, {%8,%9}, {%0,%1,%2,%3};"
        : "+f"(d[0]), "+f"(d[1]), "+f"(d[2]), "+f"(d[3])
        : "r"(a[0]), "r"(a[1]), "r"(a[2]), "r"(a[3]), "r"(b0), "r"(b1));
}
// 3-term split GEMM step on one (gate, kt) B fragment
__device__ __forceinline__ void mma3(float* d, const uint32_t* ah,
                                     const uint32_t* al, uint4 b) {
    mma16816(d, ah, b.x, b.y);   // hi * hi
    mma16816(d, al, b.x, b.y);   // lo * hi
    mma16816(d, ah, b.z, b.w);   // hi * lo
}

// epilogue for one (m-tile, row-parity): two h elements (e=0,1)
__device__ __forceinline__ void epi(
    float Dr0, float Dz0, float Dn0,
    float Dr1, float Dz1, float Dn1,
    float4 px,
    float4 b40, float4 wir0, float4 wiz0, float4 wn0,
    float4 b41, float4 wir1, float4 wiz1, float4 wn1,
    float4 lw0, float4 lw1,
    uint32_t ah, uint32_t al,
    uint32_t& nh, uint32_t& nl,
    float4& la)
{
    float hold0 = bflo(ah) + bflo(al);
    float hold1 = bfhi(ah) + bfhi(al);

    float gr0 = Dr0 + b40.x;
    gr0 = fmaf(px.x, wir0.x, gr0); gr0 = fmaf(px.y, wir0.y, gr0);
    gr0 = fmaf(px.z, wir0.z, gr0); gr0 = fmaf(px.w, wir0.w, gr0);
    float gz0 = Dz0 + b40.y;
    gz0 = fmaf(px.x, wiz0.x, gz0); gz0 = fmaf(px.y, wiz0.y, gz0);
    gz0 = fmaf(px.z, wiz0.z, gz0); gz0 = fmaf(px.w, wiz0.w, gz0);
    float gi0 = b40.w;
    gi0 = fmaf(px.x, wn0.x, gi0); gi0 = fmaf(px.y, wn0.y, gi0);
    gi0 = fmaf(px.z, wn0.z, gi0); gi0 = fmaf(px.w, wn0.w, gi0);
    float r0 = fsigmoid(gr0);
    float z0 = fsigmoid(gz0);
    float n0 = ftanh(fmaf(r0, Dn0 + b40.z, gi0));
    float h0 = fmaf(z0, hold0 - n0, n0);

    float gr1 = Dr1 + b41.x;
    gr1 = fmaf(px.x, wir1.x, gr1); gr1 = fmaf(px.y, wir1.y, gr1);
    gr1 = fmaf(px.z, wir1.z, gr1); gr1 = fmaf(px.w, wir1.w, gr1);
    float gz1 = Dz1 + b41.y;
    gz1 = fmaf(px.x, wiz1.x, gz1); gz1 = fmaf(px.y, wiz1.y, gz1);
    gz1 = fmaf(px.z, wiz1.z, gz1); gz1 = fmaf(px.w, wiz1.w, gz1);
    float gi1 = b41.w;
    gi1 = fmaf(px.x, wn1.x, gi1); gi1 = fmaf(px.y, wn1.y, gi1);
    gi1 = fmaf(px.z, wn1.z, gi1); gi1 = fmaf(px.w, wn1.w, gi1);
    float r1 = fsigmoid(gr1);
    float z1 = fsigmoid(gz1);
    float n1 = ftanh(fmaf(r1, Dn1 + b41.z, gi1));
    float h1 = fmaf(z1, hold1 - n1, n1);

    la.x = fmaf(h0, lw0.x, la.x); la.x = fmaf(h1, lw1.x, la.x);
    la.y = fmaf(h0, lw0.y, la.y); la.y = fmaf(h1, lw1.y, la.y);
    la.z = fmaf(h0, lw0.z, la.z); la.z = fmaf(h1, lw1.z, la.z);
    la.w = fmaf(h0, lw0.w, la.w); la.w = fmaf(h1, lw1.w, la.w);

    split2(h0, h1, nh, nl);
}

__device__ __forceinline__ void reduce4(float4& v) {
#pragma unroll
    for (int m = 1; m <= 2; m <<= 1) {
        v.x += __shfl_xor_sync(0xffffffffu, v.x, m);
        v.y += __shfl_xor_sync(0xffffffffu, v.y, m);
        v.z += __shfl_xor_sync(0xffffffffu, v.z, m);
        v.w += __shfl_xor_sync(0xffffffffu, v.w, m);
    }
}

__global__ void __launch_bounds__(NT, 1)
gru_encdec_mma2(const float* __restrict__ seq,
                const float* __restrict__ enc_Wih, const float* __restrict__ enc_Whh,
                const float* __restrict__ enc_bih, const float* __restrict__ enc_bhh,
                const float* __restrict__ dec_Wih, const float* __restrict__ dec_Whh,
                const float* __restrict__ dec_bih, const float* __restrict__ dec_bhh,
                const float* __restrict__ lin_W, const float* __restrict__ lin_b,
                float* __restrict__ out) {
    extern __shared__ char smem[];
    const int tid = threadIdx.x;
    const int warp = tid >> 5;
    const int lane = tid & 31;
    const int g = lane >> 2;
    const int tc = lane & 3;

    // ---------------- one-time weight prep ----------------
    uint4* bfr = (uint4*)(smem + OFF_BF);
    for (int idx = tid; idx < 2 * 24 * 4 * 32; idx += NT) {
        int li = idx & 31;
        int kt = (idx >> 5) & 3;
        int nt = (idx >> 7) % 24;
        int mat = idx / (32 * 4 * 24);
        const float* Whh = mat ? dec_Whh : enc_Whh;
        int n = nt * 8 + (li >> 2);
        int k0 = kt * 16 + (li & 3) * 2;
        float v0 = Whh[n * 64 + k0];
        float v1 = Whh[n * 64 + k0 + 1];
        float v2 = Whh[n * 64 + k0 + 8];
        float v3 = Whh[n * 64 + k0 + 9];
        uint4 q;
        split2(v0, v1, q.x, q.z);
        split2(v2, v3, q.y, q.w);
        bfr[idx] = q;
    }
    {
        float4* t4 = (float4*)(smem + OFF_TAB);
        for (int idx = tid; idx < 2 * 64; idx += NT) {
            int mat = idx >> 6, j = idx & 63;
            const float* Wih = mat ? dec_Wih : enc_Wih;
            const float* bih = mat ? dec_bih : enc_bih;
            const float* bhh = mat ? dec_bhh : enc_bhh;
            t4[idx * 4 + 0] = make_float4(bih[j] + bhh[j], bih[64 + j] + bhh[64 + j],
                                          bhh[128 + j], bih[128 + j]);
            t4[idx * 4 + 1] = ((const float4*)Wih)[j];
            t4[idx * 4 + 2] = ((const float4*)Wih)[64 + j];
            t4[idx * 4 + 3] = ((const float4*)Wih)[128 + j];
        }
        float4* lwt = (float4*)(smem + OFF_LWT);
        for (int j = tid; j < 64; j += NT)
            lwt[j] = make_float4(lin_W[j], lin_W[64 + j], lin_W[128 + j], lin_W[192 + j]);
        if (tid == 0) *(float4*)(smem + OFF_LNB) =
            make_float4(lin_b[0], lin_b[1], lin_b[2], lin_b[3]);
    }
    __syncthreads();

    // ---------------- per-warp state: 32 batch rows ----------------
    // tile0: rows r0+g, r0+g+8 ; tile1: rows r0+16+g, r0+24+g
    const int r0 = blockIdx.x * BATCH_PER_CTA + warp * 32 + g;
    const float4* sq = (const float4*)seq + (size_t)r0 * 51;
    float4* ob = (float4*)out + (size_t)r0 * 20;
    const float4* lwt = (const float4*)(smem + OFF_LWT);

    uint32_t aH0[4][4], aL0[4][4], aH1[4][4], aL1[4][4];
    uint32_t nH0[4][4], nL0[4][4], nH1[4][4], nL1[4][4];
#pragma unroll
    for (int k = 0; k < 4; ++k)
#pragma unroll
        for (int r = 0; r < 4; ++r) {
            aH0[k][r] = 0; aL0[k][r] = 0; aH1[k][r] = 0; aL1[k][r] = 0;
        }

    float4 px00 = make_float4(0, 0, 0, 0), px01 = px00, px10 = px00, px11 = px00;

#pragma unroll 1
    for (int t = 0; t < 70; ++t) {
        const bool dec = (t >= 50);
        if (!dec) {
            float4 a, b;
            a = sq[t];        b = sq[t + 1];
            px00 = make_float4(b.x - a.x, b.y - a.y, b.z - a.z, b.w - a.w);
            a = sq[408 + t];  b = sq[409 + t];
            px01 = make_float4(b.x - a.x, b.y - a.y, b.z - a.z, b.w - a.w);
            a = sq[816 + t];  b = sq[817 + t];
            px10 = make_float4(b.x - a.x, b.y - a.y, b.z - a.z, b.w - a.w);
            a = sq[1224 + t]; b = sq[1225 + t];
            px11 = make_float4(b.x - a.x, b.y - a.y, b.z - a.z, b.w - a.w);
        }
        const uint4* bm = bfr + (dec ? 24 * 4 * 32 : 0) + lane;
        const float4* tb = (const float4*)(smem + OFF_TAB) + (dec ? 64 * 4 : 0);

        float4 la00 = make_float4(0, 0, 0, 0), la01 = la00, la10 = la00, la11 = la00;

#pragma unroll
        for (int jt = 0; jt < 8; ++jt) {
            float dr0[4] = {0, 0, 0, 0}, dz0[4] = {0, 0, 0, 0}, dn0[4] = {0, 0, 0, 0};
            float dr1[4] = {0, 0, 0, 0}, dz1[4] = {0, 0, 0, 0}, dn1[4] = {0, 0, 0, 0};
#pragma unroll
            for (int kt = 0; kt < 4; ++kt) {
                uint4 br = bm[(jt * 4 + kt) * 32];
                uint4 bz = bm[((8 + jt) * 4 + kt) * 32];
                uint4 bn = bm[((16 + jt) * 4 + kt) * 32];
                mma3(dr0, aH0[kt], aL0[kt], br);
                mma3(dz0, aH0[kt], aL0[kt], bz);
                mma3(dn0, aH0[kt], aL0[kt], bn);
                mma3(dr1, aH1[kt], aL1[kt], br);
                mma3(dz1, aH1[kt], aL1[kt], bz);
                mma3(dn1, aH1[kt], aL1[kt], bn);
            }
            const int j0 = jt * 8 + tc * 2;
            const float4* tj = tb + (size_t)j0 * 4;
            float4 b40 = tj[0], wir0 = tj[1], wiz0 = tj[2], wn0 = tj[3];
            float4 b41 = tj[4], wir1 = tj[5], wiz1 = tj[6], wn1 = tj[7];
            float4 lw0 = lwt[j0], lw1 = lwt[j0 + 1];
            const int kt = jt >> 1;
            const int a0 = (jt & 1) * 2;
            epi(dr0[0], dz0[0], dn0[0], dr0[1], dz0[1], dn0[1], px00,
                b40, wir0, wiz0, wn0, b41, wir1, wiz1, wn1, lw0, lw1,
                aH0[kt][a0], aL0[kt][a0], nH0[kt][a0], nL0[kt][a0], la00);
            epi(dr0[2], dz0[2], dn0[2], dr0[3], dz0[3], dn0[3], px01,
                b40, wir0, wiz0, wn0, b41, wir1, wiz1, wn1, lw0, lw1,
                aH0[kt][a0 + 1], aL0[kt][a0 + 1], nH0[kt][a0 + 1], nL0[kt][a0 + 1], la01);
            epi(dr1[0], dz1[0], dn1[0], dr1[1], dz1[1], dn1[1], px10,
                b40, wir0, wiz0, wn0, b41, wir1, wiz1, wn1, lw0, lw1,
                aH1[kt][a0], aL1[kt][a0], nH1[kt][a0], nL1[kt][a0], la10);
            epi(dr1[2], dz1[2], dn1[2], dr1[3], dz1[3], dn1[3], px11,
                b40, wir0, wiz0, wn0, b41, wir1, wiz1, wn1, lw0, lw1,
                aH1[kt][a0 + 1], aL1[kt][a0 + 1], nH1[kt][a0 + 1], nL1[kt][a0 + 1], la11);
        }

        // commit new A fragments
#pragma unroll
        for (int k = 0; k < 4; ++k)
#pragma unroll
            for (int r = 0; r < 4; ++r) {
                aH0[k][r] = nH0[k][r]; aL0[k][r] = nL0[k][r];
                aH1[k][r] = nH1[k][r]; aL1[k][r] = nL1[k][r];
            }

        if (dec) {
            reduce4(la00); reduce4(la01); reduce4(la10); reduce4(la11);
            float4 lb = *(const float4*)(smem + OFF_LNB);
            float4 x00 = make_float4(la00.x + lb.x + px00.x, la00.y + lb.y + px00.y,
                                     la00.z + lb.z + px00.z, la00.w + lb.w + px00.w);
            float4 x01 = make_float4(la01.x + lb.x + px01.x, la01.y + lb.y + px01.y,
                                     la01.z + lb.z + px01.z, la01.w + lb.w + px01.w);
            float4 x10 = make_float4(la10.x + lb.x + px10.x, la10.y + lb.y + px10.y,
                                     la10.z + lb.z + px10.z, la10.w + lb.w + px10.w);
            float4 x11 = make_float4(la11.x + lb.x + px11.x, la11.y + lb.y + px11.y,
                                     la11.z + lb.z + px11.z, la11.w + lb.w + px11.w);
            px00 = x00; px01 = x01; px10 = x10; px11 = x11;
            if (tc == 0) {
                int s = t - 50;
                float4 of;
                of = sq[50];
                ob[s] = make_float4(x00.x + of.x, x00.y + of.y, x00.z + of.z, x00.w + of.w);
                of = sq[458];
                ob[s + 160] = make_float4(x01.x + of.x, x01.y + of.y, x01.z + of.z, x01.w + of.w);
                of = sq[866];
                ob[s + 320] = make_float4(x10.x + of.x, x10.y + of.y, x10.z + of.z, x10.w + of.w);
                of = sq[1274];
                ob[s + 480] = make_float4(x11.x + of.x, x11.y + of.y, x11.z + of.z, x11.w + of.w);
            }
        }
    }
}

extern "C" void kernel_launch(void* const* d_in, const int* in_sizes, int n_in,
                              void* d_out, int out_size) {
    const float* seq     = (const float*)d_in[0];
    const float* enc_Wih = (const float*)d_in[1];
    const float* enc_Whh = (const float*)d_in[2];
    const float* enc_bih = (const float*)d_in[3];
    const float* enc_bhh = (const float*)d_in[4];
    const float* dec_Wih = (const float*)d_in[5];
    const float* dec_Whh = (const float*)d_in[6];
    const float* dec_bih = (const float*)d_in[7];
    const float* dec_bhh = (const float*)d_in[8];
    const float* lin_W   = (const float*)d_in[9];
    const float* lin_b   = (const float*)d_in[10];
    float* out = (float*)d_out;

    cudaFuncSetAttribute(gru_encdec_mma2,
                         cudaFuncAttributeMaxDynamicSharedMemorySize, SMEM_TOTAL);

    const int B = 131072;
    gru_encdec_mma2<<<B / BATCH_PER_CTA, NT, SMEM_TOTAL>>>(
        seq, enc_Wih, enc_Whh, enc_bih, enc_bhh,
        dec_Wih, dec_Whh, dec_bih, dec_bhh, lin_W, lin_b, out);
}

// round 10
// speedup vs baseline: 1.0660x; 1.0660x over previous
#include <cuda_runtime.h>
#include <stdint.h>

#define NT 256            // 8 warps; 32 batch rows per warp
#define BATCH_PER_CTA 256

// ---- smem layout (bytes) ----
#define OFF_BF    0         // [2 mats][24 nt][5 kt][32 lanes] uint4 = 122880
#define OFF_STAGE 122880    // [8 warps][16 slots][32 lanes] uint4  = 65536
#define OFF_WN    188416    // [2][64] float4 (Wih n-gate rows)     = 2048
#define OFF_BIHN  190464    // [2][64] float                        = 512
#define OFF_LWT   190976    // [64] float4                          = 1024
#define OFF_LNB   192000    // float4
#define SMEM_TOTAL 192032

// ---------------- helpers ----------------
__device__ __forceinline__ uint32_t f2bf(float f) {
    uint16_t u;
    asm("cvt.rn.bf16.f32 %0, %1;" : "=h"(u) : "f"(f));
    return (uint32_t)u;
}
__device__ __forceinline__ float bfval(uint32_t u16) {
    return __uint_as_float(u16 << 16);
}
__device__ __forceinline__ float bfhi(uint32_t u32) {
    return __uint_as_float(u32 & 0xffff0000u);
}
__device__ __forceinline__ float bflo(uint32_t u32) {
    return __uint_as_float(u32 << 16);
}
// pack {hi16=cvt(vhi), lo16=cvt(vlo)} in one instruction
__device__ __forceinline__ uint32_t cvt2(float vhi, float vlo) {
    uint32_t r;
    asm("cvt.rn.satfinite.bf16x2.f32 %0, %1, %2;" : "=r"(r) : "f"(vhi), "f"(vlo));
    return r;
}
// split (v0 -> lo16 lane, v1 -> hi16 lane) into hi-part + residual-part
__device__ __forceinline__ void split2c(float v0, float v1, uint32_t& hi, uint32_t& lo) {
    hi = cvt2(v1, v0);
    float r0 = v0 - bflo(hi);
    float r1 = v1 - bfhi(hi);
    lo = cvt2(r1, r0);
}
__device__ __forceinline__ float fex2(float x) {
    float r; asm("ex2.approx.f32 %0, %1;" : "=f"(r) : "f"(x)); return r;
}
__device__ __forceinline__ float frcp(float x) {
    float r; asm("rcp.approx.f32 %0, %1;" : "=f"(r) : "f"(x)); return r;
}
__device__ __forceinline__ float fsigmoid(float x) {
    return frcp(1.0f + fex2(-1.4426950408889634f * x));
}
__device__ __forceinline__ float ftanh(float x) {
    float a = fabsf(x);
    float t = 1.0f - 2.0f * frcp(fex2(2.8853900817779268f * a) + 1.0f);
    return copysignf(t, x);
}
__device__ __forceinline__ void mma16816(float* d, const uint32_t* a,
                                         uint32_t b0, uint32_t b1) {
    asm volatile(
        "mma.sync.aligned.m16n8k16.row.col.f32.bf16.bf16.f32 "
        "{%0,%1,%2,%3}, {%4,%5,%6,%7}, {%8,%9}, {%0,%1,%2,%3};"
        : "+f"(d[0]), "+f"(d[1]), "+f"(d[2]), "+f"(d[3])
        : "r"(a[0]), "r"(a[1]), "r"(a[2]), "r"(a[3]), "r"(b0), "r"(b1));
}
__device__ __forceinline__ void mma3(float* d, const uint32_t* ah,
                                     const uint32_t* al, uint4 b) {
    mma16816(d, ah, b.x, b.y);   // hi * hi
    mma16816(d, al, b.x, b.y);   // lo * hi
    mma16816(d, ah, b.z, b.w);   // hi * lo
}

// folded K=80 weight matrix element W~[n][k]
__device__ __forceinline__ float wfold(const float* Whh, const float* Wih,
                                       const float* bih, const float* bhh,
                                       int n, int k) {
    if (k < 64) return Whh[n * 64 + k];
    if (k < 68) return (n < 128) ? Wih[n * 4 + (k - 64)] : 0.0f;
    if (k == 68) return (n < 128) ? (bih[n] + bhh[n]) : bhh[n];
    return 0.0f;
}

// build kt=4 A tile from px (cols 64-67 = px, col 68 = 1.0)
__device__ __forceinline__ void build_kt4(int tc, float4 pa, float4 pb,
                                          uint32_t* h4, uint32_t* l4) {
    float a0, a1, b0, b1;
    if (tc == 0)      { a0 = pa.x; a1 = pa.y; b0 = pb.x; b1 = pb.y; }
    else if (tc == 1) { a0 = pa.z; a1 = pa.w; b0 = pb.z; b1 = pb.w; }
    else if (tc == 2) { a0 = 1.f; a1 = 0.f; b0 = 1.f; b1 = 0.f; }
    else              { a0 = 0.f; a1 = 0.f; b0 = 0.f; b1 = 0.f; }
    split2c(a0, a1, h4[0], l4[0]);
    split2c(b0, b1, h4[1], l4[1]);
    h4[2] = h4[3] = l4[2] = l4[3] = 0;
}

// epilogue for one row, two h columns (j0, j0+1)
template <bool DEC>
__device__ __forceinline__ void epi2(
    float Dr0, float Dz0, float Dn0, float Dr1, float Dz1, float Dn1,
    float4 px, float4 wn0, float bn0, float4 wn1, float bn1,
    float4 lw0, float4 lw1,
    uint32_t ah, uint32_t al, uint32_t& nh, uint32_t& nl, float4& la)
{
    float hold0 = bflo(ah) + bflo(al);
    float hold1 = bfhi(ah) + bfhi(al);

    float r0 = fsigmoid(Dr0);
    float z0 = fsigmoid(Dz0);
    float gi0 = bn0;
    gi0 = fmaf(px.x, wn0.x, gi0); gi0 = fmaf(px.y, wn0.y, gi0);
    gi0 = fmaf(px.z, wn0.z, gi0); gi0 = fmaf(px.w, wn0.w, gi0);
    float n0 = ftanh(fmaf(r0, Dn0, gi0));
    float h0 = fmaf(z0, hold0 - n0, n0);

    float r1 = fsigmoid(Dr1);
    float z1 = fsigmoid(Dz1);
    float gi1 = bn1;
    gi1 = fmaf(px.x, wn1.x, gi1); gi1 = fmaf(px.y, wn1.y, gi1);
    gi1 = fmaf(px.z, wn1.z, gi1); gi1 = fmaf(px.w, wn1.w, gi1);
    float n1 = ftanh(fmaf(r1, Dn1, gi1));
    float h1 = fmaf(z1, hold1 - n1, n1);

    if (DEC) {
        la.x = fmaf(h0, lw0.x, la.x); la.x = fmaf(h1, lw1.x, la.x);
        la.y = fmaf(h0, lw0.y, la.y); la.y = fmaf(h1, lw1.y, la.y);
        la.z = fmaf(h0, lw0.z, la.z); la.z = fmaf(h1, lw1.z, la.z);
        la.w = fmaf(h0, lw0.w, la.w); la.w = fmaf(h1, lw1.w, la.w);
    }
    split2c(h0, h1, nh, nl);
}

__device__ __forceinline__ void reduce4(float4& v) {
#pragma unroll
    for (int m = 1; m <= 2; m <<= 1) {
        v.x += __shfl_xor_sync(0xffffffffu, v.x, m);
        v.y += __shfl_xor_sync(0xffffffffu, v.y, m);
        v.z += __shfl_xor_sync(0xffffffffu, v.z, m);
        v.w += __shfl_xor_sync(0xffffffffu, v.w, m);
    }
}

// one GRU step for 32 batch rows (2 m-tiles) owned by this warp
template <bool DEC>
__device__ __forceinline__ void gru_step(
    const uint4* bm, const float4* wnT, const float* bnT,
    const float4* lwt, uint4* stage, int tc,
    uint32_t (&aH0)[5][4], uint32_t (&aL0)[5][4],
    uint32_t (&aH1)[5][4], uint32_t (&aL1)[5][4],
    float4 px00, float4 px01, float4 px10, float4 px11,
    float4& la00, float4& la01, float4& la10, float4& la11)
{
    build_kt4(tc, px00, px01, aH0[4], aL0[4]);
    build_kt4(tc, px10, px11, aH1[4], aL1[4]);

#pragma unroll
    for (int jt = 0; jt < 8; ++jt) {
        float dr0[4] = {0, 0, 0, 0}, dz0[4] = {0, 0, 0, 0}, dn0[4] = {0, 0, 0, 0};
        float dr1[4] = {0, 0, 0, 0}, dz1[4] = {0, 0, 0, 0}, dn1[4] = {0, 0, 0, 0};
#pragma unroll
        for (int kt = 0; kt < 5; ++kt) {
            uint4 br = bm[(jt * 5 + kt) * 32];
            uint4 bz = bm[((8 + jt) * 5 + kt) * 32];
            uint4 bn = bm[((16 + jt) * 5 + kt) * 32];
            mma3(dr0, aH0[kt], aL0[kt], br);
            mma3(dr1, aH1[kt], aL1[kt], br);
            mma3(dz0, aH0[kt], aL0[kt], bz);
            mma3(dz1, aH1[kt], aL1[kt], bz);
            mma3(dn0, aH0[kt], aL0[kt], bn);
            mma3(dn1, aH1[kt], aL1[kt], bn);
        }
        const int j0 = jt * 8 + tc * 2;
        float4 wn0 = wnT[j0], wn1 = wnT[j0 + 1];
        float bn0 = bnT[j0], bn1 = bnT[j0 + 1];
        float4 lw0, lw1;
        if (DEC) { lw0 = lwt[j0]; lw1 = lwt[j0 + 1]; }
        const int kt = jt >> 1;
        const int a0 = (jt & 1) * 2;
        uint32_t h00, l00, h01, l01, h10, l10, h11, l11;
        epi2<DEC>(dr0[0], dz0[0], dn0[0], dr0[1], dz0[1], dn0[1], px00,
                  wn0, bn0, wn1, bn1, lw0, lw1,
                  aH0[kt][a0], aL0[kt][a0], h00, l00, la00);
        epi2<DEC>(dr0[2], dz0[2], dn0[2], dr0[3], dz0[3], dn0[3], px01,
                  wn0, bn0, wn1, bn1, lw0, lw1,
                  aH0[kt][a0 + 1], aL0[kt][a0 + 1], h01, l01, la01);
        epi2<DEC>(dr1[0], dz1[0], dn1[0], dr1[1], dz1[1], dn1[1], px10,
                  wn0, bn0, wn1, bn1, lw0, lw1,
                  aH1[kt][a0], aL1[kt][a0], h10, l10, la10);
        epi2<DEC>(dr1[2], dz1[2], dn1[2], dr1[3], dz1[3], dn1[3], px11,
                  wn0, bn0, wn1, bn1, lw0, lw1,
                  aH1[kt][a0 + 1], aL1[kt][a0 + 1], h11, l11, la11);
        stage[(jt * 2) * 32]     = make_uint4(h00, h01, l00, l01);
        stage[(jt * 2 + 1) * 32] = make_uint4(h10, h11, l10, l11);
    }
    // reload new A fragments (warp-private smem; same-thread st->ld ordered)
#pragma unroll
    for (int jt = 0; jt < 8; ++jt) {
        const int kt = jt >> 1;
        const int a0 = (jt & 1) * 2;
        uint4 v0 = stage[(jt * 2) * 32];
        aH0[kt][a0] = v0.x; aH0[kt][a0 + 1] = v0.y;
        aL0[kt][a0] = v0.z; aL0[kt][a0 + 1] = v0.w;
        uint4 v1 = stage[(jt * 2 + 1) * 32];
        aH1[kt][a0] = v1.x; aH1[kt][a0 + 1] = v1.y;
        aL1[kt][a0] = v1.z; aL1[kt][a0 + 1] = v1.w;
    }
}

__global__ void __launch_bounds__(NT, 1)
gru_encdec_mma3(const float* __restrict__ seq,
                const float* __restrict__ enc_Wih, const float* __restrict__ enc_Whh,
                const float* __restrict__ enc_bih, const float* __restrict__ enc_bhh,
                const float* __restrict__ dec_Wih, const float* __restrict__ dec_Whh,
                const float* __restrict__ dec_bih, const float* __restrict__ dec_bhh,
                const float* __restrict__ lin_W, const float* __restrict__ lin_b,
                float* __restrict__ out) {
    extern __shared__ char smem[];
    const int tid = threadIdx.x;
    const int warp = tid >> 5;
    const int lane = tid & 31;
    const int g = lane >> 2;
    const int tc = lane & 3;

    // ---------------- one-time weight prep ----------------
    uint4* bfr = (uint4*)(smem + OFF_BF);
    for (int idx = tid; idx < 2 * 24 * 5 * 32; idx += NT) {
        int li = idx & 31;
        int kt = (idx >> 5) % 5;
        int nt = (idx / (32 * 5)) % 24;
        int mat = idx / (32 * 5 * 24);
        const float* Whh = mat ? dec_Whh : enc_Whh;
        const float* Wih = mat ? dec_Wih : enc_Wih;
        const float* bih = mat ? dec_bih : enc_bih;
        const float* bhh = mat ? dec_bhh : enc_bhh;
        int n = nt * 8 + (li >> 2);
        int k0 = kt * 16 + (li & 3) * 2;
        float v0 = wfold(Whh, Wih, bih, bhh, n, k0);
        float v1 = wfold(Whh, Wih, bih, bhh, n, k0 + 1);
        float v2 = wfold(Whh, Wih, bih, bhh, n, k0 + 8);
        float v3 = wfold(Whh, Wih, bih, bhh, n, k0 + 9);
        uint4 q;
        split2c(v0, v1, q.x, q.z);
        split2c(v2, v3, q.y, q.w);
        bfr[idx] = q;
    }
    {
        float4* wnT = (float4*)(smem + OFF_WN);
        float* bnT = (float*)(smem + OFF_BIHN);
        float4* lwt = (float4*)(smem + OFF_LWT);
        for (int idx = tid; idx < 2 * 64; idx += NT) {
            int mat = idx >> 6, j = idx & 63;
            const float* Wih = mat ? dec_Wih : enc_Wih;
            const float* bih = mat ? dec_bih : enc_bih;
            wnT[idx] = ((const float4*)Wih)[128 + j];
            bnT[idx] = bih[128 + j];
        }
        for (int j = tid; j < 64; j += NT)
            lwt[j] = make_float4(lin_W[j], lin_W[64 + j], lin_W[128 + j], lin_W[192 + j]);
        if (tid == 0) *(float4*)(smem + OFF_LNB) =
            make_float4(lin_b[0], lin_b[1], lin_b[2], lin_b[3]);
    }
    __syncthreads();

    // ---------------- per-warp state: 32 batch rows ----------------
    const int r0 = blockIdx.x * BATCH_PER_CTA + warp * 32 + g;
    const float4* sq = (const float4*)seq + (size_t)r0 * 51;
    float4* ob = (float4*)out + (size_t)r0 * 20;
    const float4* wnTb = (const float4*)(smem + OFF_WN);
    const float* bnTb = (const float*)(smem + OFF_BIHN);
    const float4* lwt = (const float4*)(smem + OFF_LWT);
    uint4* stage = (uint4*)(smem + OFF_STAGE) + warp * 512 + lane;

    uint32_t aH0[5][4], aL0[5][4], aH1[5][4], aL1[5][4];
#pragma unroll
    for (int k = 0; k < 5; ++k)
#pragma unroll
        for (int r = 0; r < 4; ++r) {
            aH0[k][r] = 0; aL0[k][r] = 0; aH1[k][r] = 0; aL1[k][r] = 0;
        }

    float4 px00 = make_float4(0, 0, 0, 0), px01 = px00, px10 = px00, px11 = px00;
    float4 la00, la01, la10, la11;

    // ---------------- encoder: 50 steps ----------------
    const uint4* bmE = bfr + lane;
#pragma unroll 1
    for (int t = 0; t < 50; ++t) {
        float4 a, b;
        a = sq[t];        b = sq[t + 1];
        px00 = make_float4(b.x - a.x, b.y - a.y, b.z - a.z, b.w - a.w);
        a = sq[408 + t];  b = sq[409 + t];
        px01 = make_float4(b.x - a.x, b.y - a.y, b.z - a.z, b.w - a.w);
        a = sq[816 + t];  b = sq[817 + t];
        px10 = make_float4(b.x - a.x, b.y - a.y, b.z - a.z, b.w - a.w);
        a = sq[1224 + t]; b = sq[1225 + t];
        px11 = make_float4(b.x - a.x, b.y - a.y, b.z - a.z, b.w - a.w);
        gru_step<false>(bmE, wnTb, bnTb, lwt, stage, tc,
                        aH0, aL0, aH1, aL1, px00, px01, px10, px11,
                        la00, la01, la10, la11);
    }

    // ---------------- decoder: 20 steps ----------------
    const uint4* bmD = bfr + 24 * 5 * 32 + lane;
    const float4* wnTd = wnTb + 64;
    const float* bnTd = bnTb + 64;
    const float4 lnb = *(const float4*)(smem + OFF_LNB);
    const float4 of0 = sq[50], of1 = sq[458], of2 = sq[866], of3 = sq[1274];

#pragma unroll 1
    for (int s = 0; s < 20; ++s) {
        la00 = make_float4(0, 0, 0, 0); la01 = la00; la10 = la00; la11 = la00;
        gru_step<true>(bmD, wnTd, bnTd, lwt, stage, tc,
                       aH0, aL0, aH1, aL1, px00, px01, px10, px11,
                       la00, la01, la10, la11);
        reduce4(la00); reduce4(la01); reduce4(la10); reduce4(la11);
        float4 x00 = make_float4(la00.x + lnb.x + px00.x, la00.y + lnb.y + px00.y,
                                 la00.z + lnb.z + px00.z, la00.w + lnb.w + px00.w);
        float4 x01 = make_float4(la01.x + lnb.x + px01.x, la01.y + lnb.y + px01.y,
                                 la01.z + lnb.z + px01.z, la01.w + lnb.w + px01.w);
        float4 x10 = make_float4(la10.x + lnb.x + px10.x, la10.y + lnb.y + px10.y,
                                 la10.z + lnb.z + px10.z, la10.w + lnb.w + px10.w);
        float4 x11 = make_float4(la11.x + lnb.x + px11.x, la11.y + lnb.y + px11.y,
                                 la11.z + lnb.z + px11.z, la11.w + lnb.w + px11.w);
        px00 = x00; px01 = x01; px10 = x10; px11 = x11;
        if (tc == 0) {
            ob[s]       = make_float4(x00.x + of0.x, x00.y + of0.y, x00.z + of0.z, x00.w + of0.w);
            ob[s + 160] = make_float4(x01.x + of1.x, x01.y + of1.y, x01.z + of1.z, x01.w + of1.w);
            ob[s + 320] = make_float4(x10.x + of2.x, x10.y + of2.y, x10.z + of2.z, x10.w + of2.w);
            ob[s + 480] = make_float4(x11.x + of3.x, x11.y + of3.y, x11.z + of3.z, x11.w + of3.w);
        }
    }
}

extern "C" void kernel_launch(void* const* d_in, const int* in_sizes, int n_in,
                              void* d_out, int out_size) {
    const float* seq     = (const float*)d_in[0];
    const float* enc_Wih = (const float*)d_in[1];
    const float* enc_Whh = (const float*)d_in[2];
    const float* enc_bih = (const float*)d_in[3];
    const float* enc_bhh = (const float*)d_in[4];
    const float* dec_Wih = (const float*)d_in[5];
    const float* dec_Whh = (const float*)d_in[6];
    const float* dec_bih = (const float*)d_in[7];
    const float* dec_bhh = (const float*)d_in[8];
    const float* lin_W   = (const float*)d_in[9];
    const float* lin_b   = (const float*)d_in[10];
    float* out = (float*)d_out;

    cudaFuncSetAttribute(gru_encdec_mma3,
                         cudaFuncAttributeMaxDynamicSharedMemorySize, SMEM_TOTAL);

    const int B = 131072;
    gru_encdec_mma3<<<B / BATCH_PER_CTA, NT, SMEM_TOTAL>>>(
        seq, enc_Wih, enc_Whh, enc_bih, enc_bhh,
        dec_Wih, dec_Whh, dec_bih, dec_bhh, lin_W, lin_b, out);
}

// round 11
// speedup vs baseline: 1.1078x; 1.0392x over previous
#include <cuda_runtime.h>
#include <stdint.h>

#define NT 512            // 16 warps; 16 batch rows per warp
#define BATCH_PER_CTA 256

// ---- smem layout (bytes) ----
#define OFF_BF    0         // [2 mats][24 nt][5 kt][32 lanes] uint4 = 122880
#define OFF_STAGE 122880    // [16 warps][8 slots][32 lanes] uint4  = 65536
#define OFF_WN    188416    // [2][64] float4 (Wih n-gate rows)     = 2048
#define OFF_BIHN  190464    // [2][64] float                        = 512
#define OFF_LWT   190976    // [64] float4                          = 1024
#define OFF_LNB   192000    // float4
#define SMEM_TOTAL 192032

// ---------------- helpers ----------------
__device__ __forceinline__ float bfhi(uint32_t u32) {
    return __uint_as_float(u32 & 0xffff0000u);
}
__device__ __forceinline__ float bflo(uint32_t u32) {
    return __uint_as_float(u32 << 16);
}
__device__ __forceinline__ uint32_t cvt2(float vhi, float vlo) {
    uint32_t r;
    asm("cvt.rn.satfinite.bf16x2.f32 %0, %1, %2;" : "=r"(r) : "f"(vhi), "f"(vlo));
    return r;
}
// split (v0 -> lo16, v1 -> hi16) into hi-part + residual-part
__device__ __forceinline__ void split2c(float v0, float v1, uint32_t& hi, uint32_t& lo) {
    hi = cvt2(v1, v0);
    float r0 = v0 - bflo(hi);
    float r1 = v1 - bfhi(hi);
    lo = cvt2(r1, r0);
}
__device__ __forceinline__ float fex2(float x) {
    float r; asm("ex2.approx.f32 %0, %1;" : "=f"(r) : "f"(x)); return r;
}
__device__ __forceinline__ float frcp(float x) {
    float r; asm("rcp.approx.f32 %0, %1;" : "=f"(r) : "f"(x)); return r;
}
__device__ __forceinline__ float fsigmoid(float x) {
    return frcp(1.0f + fex2(-1.4426950408889634f * x));
}
__device__ __forceinline__ float ftanh(float x) {
    float a = fabsf(x);
    float t = 1.0f - 2.0f * frcp(fex2(2.8853900817779268f * a) + 1.0f);
    return copysignf(t, x);
}
__device__ __forceinline__ void mma16816(float* d, const uint32_t* a,
                                         uint32_t b0, uint32_t b1) {
    asm volatile(
        "mma.sync.aligned.m16n8k16.row.col.f32.bf16.bf16.f32 "
        "{%0,%1,%2,%3}, {%4,%5,%6,%7}, {%8,%9}, {%0,%1,%2,%3};"
        : "+f"(d[0]), "+f"(d[1]), "+f"(d[2]), "+f"(d[3])
        : "r"(a[0]), "r"(a[1]), "r"(a[2]), "r"(a[3]), "r"(b0), "r"(b1));
}

// folded K=80 weight matrix element W~[n][k]
__device__ __forceinline__ float wfold(const float* Whh, const float* Wih,
                                       const float* bih, const float* bhh,
                                       int n, int k) {
    if (k < 64) return Whh[n * 64 + k];
    if (k < 68) return (n < 128) ? Wih[n * 4 + (k - 64)] : 0.0f;
    if (k == 68) return (n < 128) ? (bih[n] + bhh[n]) : bhh[n];
    return 0.0f;
}

// build kt=4 A tile from px (cols 64-67 = px, col 68 = 1.0)
__device__ __forceinline__ void build_kt4(int tc, float4 pa, float4 pb,
                                          uint32_t* h4, uint32_t* l4) {
    float a0, a1, b0, b1;
    if (tc == 0)      { a0 = pa.x; a1 = pa.y; b0 = pb.x; b1 = pb.y; }
    else if (tc == 1) { a0 = pa.z; a1 = pa.w; b0 = pb.z; b1 = pb.w; }
    else if (tc == 2) { a0 = 1.f; a1 = 0.f; b0 = 1.f; b1 = 0.f; }
    else              { a0 = 0.f; a1 = 0.f; b0 = 0.f; b1 = 0.f; }
    split2c(a0, a1, h4[0], l4[0]);
    split2c(b0, b1, h4[1], l4[1]);
    h4[2] = h4[3] = l4[2] = l4[3] = 0;
}

// epilogue for one row, two h columns (j0, j0+1)
template <bool DEC>
__device__ __forceinline__ void epi2(
    float Dr0, float Dz0, float Dn0, float Dr1, float Dz1, float Dn1,
    float4 px, float4 wn0, float bn0, float4 wn1, float bn1,
    float4 lw0, float4 lw1,
    uint32_t ah, uint32_t al, uint32_t& nh, uint32_t& nl, float4& la)
{
    float hold0 = bflo(ah) + bflo(al);
    float hold1 = bfhi(ah) + bfhi(al);

    float r0 = fsigmoid(Dr0);
    float z0 = fsigmoid(Dz0);
    float gi0 = bn0;
    gi0 = fmaf(px.x, wn0.x, gi0); gi0 = fmaf(px.y, wn0.y, gi0);
    gi0 = fmaf(px.z, wn0.z, gi0); gi0 = fmaf(px.w, wn0.w, gi0);
    float n0 = ftanh(fmaf(r0, Dn0, gi0));
    float h0 = fmaf(z0, hold0 - n0, n0);

    float r1 = fsigmoid(Dr1);
    float z1 = fsigmoid(Dz1);
    float gi1 = bn1;
    gi1 = fmaf(px.x, wn1.x, gi1); gi1 = fmaf(px.y, wn1.y, gi1);
    gi1 = fmaf(px.z, wn1.z, gi1); gi1 = fmaf(px.w, wn1.w, gi1);
    float n1 = ftanh(fmaf(r1, Dn1, gi1));
    float h1 = fmaf(z1, hold1 - n1, n1);

    if (DEC) {
        la.x = fmaf(h0, lw0.x, la.x); la.x = fmaf(h1, lw1.x, la.x);
        la.y = fmaf(h0, lw0.y, la.y); la.y = fmaf(h1, lw1.y, la.y);
        la.z = fmaf(h0, lw0.z, la.z); la.z = fmaf(h1, lw1.z, la.z);
        la.w = fmaf(h0, lw0.w, la.w); la.w = fmaf(h1, lw1.w, la.w);
    }
    split2c(h0, h1, nh, nl);
}

__device__ __forceinline__ void reduce4(float4& v) {
#pragma unroll
    for (int m = 1; m <= 2; m <<= 1) {
        v.x += __shfl_xor_sync(0xffffffffu, v.x, m);
        v.y += __shfl_xor_sync(0xffffffffu, v.y, m);
        v.z += __shfl_xor_sync(0xffffffffu, v.z, m);
        v.w += __shfl_xor_sync(0xffffffffu, v.w, m);
    }
}

// one GRU step for 16 batch rows (1 m-tile) owned by this warp
template <bool DEC>
__device__ __forceinline__ void gru_step(
    const uint4* bm, const float4* wnT, const float* bnT,
    const float4* lwt, uint4* stage, int tc,
    uint32_t (&aH)[5][4], uint32_t (&aL)[5][4],
    float4 px0, float4 px1, float4& la0, float4& la1)
{
    build_kt4(tc, px0, px1, aH[4], aL[4]);

#pragma unroll
    for (int jt = 0; jt < 8; ++jt) {
        float dr[4] = {0, 0, 0, 0}, dz[4] = {0, 0, 0, 0}, dn[4] = {0, 0, 0, 0};
#pragma unroll
        for (int kt = 0; kt < 5; ++kt) {
            uint4 br = bm[(jt * 5 + kt) * 32];
            uint4 bz = bm[((8 + jt) * 5 + kt) * 32];
            uint4 bn = bm[((16 + jt) * 5 + kt) * 32];
            // interleaved: consecutive HMMAs hit different accumulators
            mma16816(dr, aH[kt], br.x, br.y);
            mma16816(dz, aH[kt], bz.x, bz.y);
            mma16816(dn, aH[kt], bn.x, bn.y);
            mma16816(dr, aL[kt], br.x, br.y);
            mma16816(dz, aL[kt], bz.x, bz.y);
            mma16816(dn, aL[kt], bn.x, bn.y);
            mma16816(dr, aH[kt], br.z, br.w);
            mma16816(dz, aH[kt], bz.z, bz.w);
            mma16816(dn, aH[kt], bn.z, bn.w);
        }
        const int j0 = jt * 8 + tc * 2;
        float4 wn0 = wnT[j0], wn1 = wnT[j0 + 1];
        float bn0 = bnT[j0], bn1 = bnT[j0 + 1];
        float4 lw0, lw1;
        if (DEC) { lw0 = lwt[j0]; lw1 = lwt[j0 + 1]; }
        const int kt = jt >> 1;
        const int a0 = (jt & 1) * 2;
        uint32_t h0, l0, h1, l1;
        epi2<DEC>(dr[0], dz[0], dn[0], dr[1], dz[1], dn[1], px0,
                  wn0, bn0, wn1, bn1, lw0, lw1,
                  aH[kt][a0], aL[kt][a0], h0, l0, la0);
        epi2<DEC>(dr[2], dz[2], dn[2], dr[3], dz[3], dn[3], px1,
                  wn0, bn0, wn1, bn1, lw0, lw1,
                  aH[kt][a0 + 1], aL[kt][a0 + 1], h1, l1, la1);
        stage[jt * 32] = make_uint4(h0, h1, l0, l1);
    }
    // reload new A fragments (warp-private smem; same-thread st->ld ordered)
#pragma unroll
    for (int jt = 0; jt < 8; ++jt) {
        const int kt = jt >> 1;
        const int a0 = (jt & 1) * 2;
        uint4 v = stage[jt * 32];
        aH[kt][a0] = v.x; aH[kt][a0 + 1] = v.y;
        aL[kt][a0] = v.z; aL[kt][a0 + 1] = v.w;
    }
}

__global__ void __launch_bounds__(NT, 1)
gru_encdec_mma4(const float* __restrict__ seq,
                const float* __restrict__ enc_Wih, const float* __restrict__ enc_Whh,
                const float* __restrict__ enc_bih, const float* __restrict__ enc_bhh,
                const float* __restrict__ dec_Wih, const float* __restrict__ dec_Whh,
                const float* __restrict__ dec_bih, const float* __restrict__ dec_bhh,
                const float* __restrict__ lin_W, const float* __restrict__ lin_b,
                float* __restrict__ out) {
    extern __shared__ char smem[];
    const int tid = threadIdx.x;
    const int warp = tid >> 5;
    const int lane = tid & 31;
    const int g = lane >> 2;
    const int tc = lane & 3;

    // ---------------- one-time weight prep ----------------
    uint4* bfr = (uint4*)(smem + OFF_BF);
    for (int idx = tid; idx < 2 * 24 * 5 * 32; idx += NT) {
        int li = idx & 31;
        int kt = (idx >> 5) % 5;
        int nt = (idx / (32 * 5)) % 24;
        int mat = idx / (32 * 5 * 24);
        const float* Whh = mat ? dec_Whh : enc_Whh;
        const float* Wih = mat ? dec_Wih : enc_Wih;
        const float* bih = mat ? dec_bih : enc_bih;
        const float* bhh = mat ? dec_bhh : enc_bhh;
        int n = nt * 8 + (li >> 2);
        int k0 = kt * 16 + (li & 3) * 2;
        float v0 = wfold(Whh, Wih, bih, bhh, n, k0);
        float v1 = wfold(Whh, Wih, bih, bhh, n, k0 + 1);
        float v2 = wfold(Whh, Wih, bih, bhh, n, k0 + 8);
        float v3 = wfold(Whh, Wih, bih, bhh, n, k0 + 9);
        uint4 q;
        split2c(v0, v1, q.x, q.z);
        split2c(v2, v3, q.y, q.w);
        bfr[idx] = q;
    }
    {
        float4* wnT = (float4*)(smem + OFF_WN);
        float* bnT = (float*)(smem + OFF_BIHN);
        float4* lwt = (float4*)(smem + OFF_LWT);
        for (int idx = tid; idx < 2 * 64; idx += NT) {
            int mat = idx >> 6, j = idx & 63;
            const float* Wih = mat ? dec_Wih : enc_Wih;
            const float* bih = mat ? dec_bih : enc_bih;
            wnT[idx] = ((const float4*)Wih)[128 + j];
            bnT[idx] = bih[128 + j];
        }
        for (int j = tid; j < 64; j += NT)
            lwt[j] = make_float4(lin_W[j], lin_W[64 + j], lin_W[128 + j], lin_W[192 + j]);
        if (tid == 0) *(float4*)(smem + OFF_LNB) =
            make_float4(lin_b[0], lin_b[1], lin_b[2], lin_b[3]);
    }
    __syncthreads();

    // ---------------- per-warp state: 16 batch rows (rows g, g+8) -----------
    const int r0 = blockIdx.x * BATCH_PER_CTA + warp * 16 + g;
    const float4* sq = (const float4*)seq + (size_t)r0 * 51;
    float4* ob = (float4*)out + (size_t)r0 * 20;
    const float4* wnTb = (const float4*)(smem + OFF_WN);
    const float* bnTb = (const float*)(smem + OFF_BIHN);
    const float4* lwt = (const float4*)(smem + OFF_LWT);
    uint4* stage = (uint4*)(smem + OFF_STAGE) + warp * 256 + lane;

    uint32_t aH[5][4], aL[5][4];
#pragma unroll
    for (int k = 0; k < 5; ++k)
#pragma unroll
        for (int r = 0; r < 4; ++r) { aH[k][r] = 0; aL[k][r] = 0; }

    float4 px0 = make_float4(0, 0, 0, 0), px1 = px0;
    float4 la0, la1;

    // ---------------- encoder: 50 steps ----------------
    const uint4* bmE = bfr + lane;
#pragma unroll 1
    for (int t = 0; t < 50; ++t) {
        float4 a, b;
        a = sq[t];       b = sq[t + 1];
        px0 = make_float4(b.x - a.x, b.y - a.y, b.z - a.z, b.w - a.w);
        a = sq[408 + t]; b = sq[409 + t];
        px1 = make_float4(b.x - a.x, b.y - a.y, b.z - a.z, b.w - a.w);
        gru_step<false>(bmE, wnTb, bnTb, lwt, stage, tc,
                        aH, aL, px0, px1, la0, la1);
    }

    // ---------------- decoder: 20 steps ----------------
    const uint4* bmD = bfr + 24 * 5 * 32 + lane;
    const float4* wnTd = wnTb + 64;
    const float* bnTd = bnTb + 64;
    const float4 lnb = *(const float4*)(smem + OFF_LNB);
    const float4 of0 = sq[50], of1 = sq[458];

#pragma unroll 1
    for (int s = 0; s < 20; ++s) {
        la0 = make_float4(0, 0, 0, 0); la1 = la0;
        gru_step<true>(bmD, wnTd, bnTd, lwt, stage, tc,
                       aH, aL, px0, px1, la0, la1);
        reduce4(la0); reduce4(la1);
        float4 x0 = make_float4(la0.x + lnb.x + px0.x, la0.y + lnb.y + px0.y,
                                la0.z + lnb.z + px0.z, la0.w + lnb.w + px0.w);
        float4 x1 = make_float4(la1.x + lnb.x + px1.x, la1.y + lnb.y + px1.y,
                                la1.z + lnb.z + px1.z, la1.w + lnb.w + px1.w);
        px0 = x0; px1 = x1;
        if (tc == 0) {
            ob[s]       = make_float4(x0.x + of0.x, x0.y + of0.y,
                                      x0.z + of0.z, x0.w + of0.w);
            ob[s + 160] = make_float4(x1.x + of1.x, x1.y + of1.y,
                                      x1.z + of1.z, x1.w + of1.w);
        }
    }
}

extern "C" void kernel_launch(void* const* d_in, const int* in_sizes, int n_in,
                              void* d_out, int out_size) {
    const float* seq     = (const float*)d_in[0];
    const float* enc_Wih = (const float*)d_in[1];
    const float* enc_Whh = (const float*)d_in[2];
    const float* enc_bih = (const float*)d_in[3];
    const float* enc_bhh = (const float*)d_in[4];
    const float* dec_Wih = (const float*)d_in[5];
    const float* dec_Whh = (const float*)d_in[6];
    const float* dec_bih = (const float*)d_in[7];
    const float* dec_bhh = (const float*)d_in[8];
    const float* lin_W   = (const float*)d_in[9];
    const float* lin_b   = (const float*)d_in[10];
    float* out = (float*)d_out;

    cudaFuncSetAttribute(gru_encdec_mma4,
                         cudaFuncAttributeMaxDynamicSharedMemorySize, SMEM_TOTAL);

    const int B = 131072;
    gru_encdec_mma4<<<B / BATCH_PER_CTA, NT, SMEM_TOTAL>>>(
        seq, enc_Wih, enc_Whh, enc_bih, enc_bhh,
        dec_Wih, dec_Whh, dec_bih, dec_bhh, lin_W, lin_b, out);
}